// round 9
// baseline (speedup 1.0000x reference)
#include <cuda_runtime.h>
#include <cuda_bf16.h>
#include <math.h>
#include <stdint.h>

#define HWD 36864
#define BD 4
#define QD 256
#define ED 128
#define NSPLIT 18
#define KS (HWD / NSPLIT)   // 2048
#define BK 32
#define KT (KS / BK)        // 64
#define TM 64               // M tile (Q rows per CTA)

// smem: double-buffered fp32 staging + single bf16 tile set
// stage: ml/pm/pl 64 rows + seg 128 rows, 128B each
#define S_ML 0
#define S_PM (64 * 128)
#define S_PL (128 * 128)
#define S_SG (192 * 128)
#define STAGE_B (320 * 128)              // 40960
// tiles (bf16, 64B rows): xw 64, p 64, tgt 128, sgm 128 rows
#define T_XW 0
#define T_P  4096
#define T_TGT 8192
#define T_SGM 16384
#define TILES_B 24576
#define SM_TILES (2 * STAGE_B)           // 81920
#define SMEM_TOTAL (SM_TILES + TILES_B)  // 106496

// ---------------- static scratch ----------------
__device__ __align__(16) __nv_bfloat162 g_P[(size_t)BD * NSPLIT * QD * ED];
__device__ float g_negsum_p[BD * NSPLIT * QD];
__device__ float g_psum_p  [BD * NSPLIT * QD];
__device__ float g_segsum_p[BD * NSPLIT * ED];
__device__ int   g_nnzs    [BD * NSPLIT];

__device__ __forceinline__ uint32_t swz64(int off) {
    return (uint32_t)(off ^ ((off >> 3) & 0x30));
}

__device__ __forceinline__ float fast_tanh(float x) {
    float y;
    asm("tanh.approx.f32 %0, %1;" : "=f"(y) : "f"(x));
    return y;
}

__device__ __forceinline__ void sts_4bf16(uint32_t addr, float a, float b,
                                          float c, float d) {
    __nv_bfloat162 lo = __floats2bfloat162_rn(a, b);
    __nv_bfloat162 hi = __floats2bfloat162_rn(c, d);
    asm volatile("st.shared.v2.b32 [%0], {%1,%2};"
                 :: "r"(addr), "r"(*(uint32_t*)&lo), "r"(*(uint32_t*)&hi));
}

#define CPA16(dst, src) \
    asm volatile("cp.async.cg.shared.global [%0], [%1], 16;" :: "r"(dst), "l"(src))

// ---------------- fused prep + 2x GEMM (64x128 tile, 2 CTAs/SM) ----------------
__global__ __launch_bounds__(256, 2) void fused_gemm_kernel(
    const float* __restrict__ ml, const float* __restrict__ pm,
    const float* __restrict__ pl, const float* __restrict__ seg)
{
    extern __shared__ __align__(16) char smem[];
    const uint32_t smem_base = (uint32_t)__cvta_generic_to_shared(smem);
    const int tid = threadIdx.x;
    const int wid = tid >> 5, lane = tid & 31;

    int bx = blockIdx.x;                 // 0..287
    const int split = bx % NSPLIT; bx /= NSPLIT;
    const int mtile = bx & 3;      bx >>= 2;
    const int b = bx;

    const int r0 = tid >> 3;              // 0..31
    const int c8 = tid & 7;               // 16B group within 128B K-chunk
    const size_t colg = (size_t)split * KS + c8 * 4;

    const float* gml = ml + ((size_t)(b * QD + mtile * TM)) * HWD + colg;
    const float* gpm = pm + ((size_t)(b * QD + mtile * TM)) * HWD + colg;
    const float* gpl = pl + ((size_t)(b * QD + mtile * TM)) * HWD + colg;
    const float* gsg = seg + ((size_t)(b * ED)) * HWD + colg;

    const int wm = wid & 1;               // 32-row half of 64
    const int wn = wid >> 1;              // 32-col quarter of 128

    const uint32_t tiles = smem_base + SM_TILES;
    const uint32_t t_xw  = tiles + T_XW;
    const uint32_t t_p   = tiles + T_P;
    const uint32_t t_tgt = tiles + T_TGT;
    const uint32_t t_sgm = tiles + T_SGM;

    float acc1[2][4][4];
    float acc2[2][4][4];
#pragma unroll
    for (int mi = 0; mi < 2; mi++)
#pragma unroll
        for (int ni = 0; ni < 4; ni++)
#pragma unroll
            for (int c = 0; c < 4; c++) { acc1[mi][ni][c] = 0.f; acc2[mi][ni][c] = 0.f; }

    float nl[2], plo[2], sl[4]; int zl[4];
#pragma unroll
    for (int k = 0; k < 2; k++) { nl[k] = plo[k] = 0.f; }
#pragma unroll
    for (int k = 0; k < 4; k++) { sl[k] = 0.f; zl[k] = 0; }

#define ISSUE_STAGE(kt_, buf_) do {                                            \
        const uint32_t sb = smem_base + (buf_) * STAGE_B;                      \
        const size_t kadv = (size_t)(kt_) * BK;                                \
        _Pragma("unroll")                                                      \
        for (int k_ = 0; k_ < 2; k_++) {                                       \
            const int row_ = r0 + 32 * k_;                                     \
            const uint32_t so = row_ * 128 + c8 * 16;                          \
            const size_t go = (size_t)row_ * HWD + kadv;                       \
            CPA16(sb + S_ML + so, gml + go);                                   \
            CPA16(sb + S_PM + so, gpm + go);                                   \
            CPA16(sb + S_PL + so, gpl + go);                                   \
        }                                                                      \
        _Pragma("unroll")                                                      \
        for (int k_ = 0; k_ < 4; k_++) {                                       \
            const int row_ = r0 + 32 * k_;                                     \
            const uint32_t so = row_ * 128 + c8 * 16;                          \
            const size_t go = (size_t)row_ * HWD + kadv;                       \
            CPA16(sb + S_SG + so, gsg + go);                                   \
        }                                                                      \
        asm volatile("cp.async.commit_group;");                                \
    } while (0)

    ISSUE_STAGE(0, 0);
    ISSUE_STAGE(1, 1);

    for (int kt = 0; kt < KT; kt++) {
        asm volatile("cp.async.wait_group 1;" ::: "memory");
        // tiles free: guaranteed by the post-MMA barrier of the previous iter

        const int sbuf = kt & 1;
        // ---- transform A part: rows r0, r0+32 of ml/pm/pl ----
#pragma unroll
        for (int k = 0; k < 2; k++) {
            const int row = r0 + 32 * k;
            const uint32_t so = row * 128 + c8 * 16;
            float4 M = *(const float4*)(smem + sbuf * STAGE_B + S_ML + so);
            float4 W = *(const float4*)(smem + sbuf * STAGE_B + S_PM + so);
            float4 L = *(const float4*)(smem + sbuf * STAGE_B + S_PL + so);
            const float* mm = (const float*)&M;
            const float* ww = (const float*)&W;
            const float* ll = (const float*)&L;
            float xw[4], qv[4];
#pragma unroll
            for (int u = 0; u < 4; u++) {
                float x = mm[u], wt = ww[u];
                xw[u] = x * wt;
                float sx = 0.5f + 0.5f * fast_tanh(0.5f * x);
                nl[k] += -__logf(fmaxf(1.f - sx, 1e-30f)) * wt;
                qv[u] = wt * (0.5f + 0.5f * fast_tanh(0.5f * ll[u]));
                plo[k] += qv[u];
            }
            const uint32_t sw = swz64(row * 64 + c8 * 8);
            sts_4bf16(t_xw + sw, xw[0], xw[1], xw[2], xw[3]);
            sts_4bf16(t_p  + sw, qv[0], qv[1], qv[2], qv[3]);
        }
        // ---- transform B part: rows r0+32k of seg ----
#pragma unroll
        for (int k = 0; k < 4; k++) {
            const int row = r0 + 32 * k;
            const uint32_t so = row * 128 + c8 * 16;
            float4 S = *(const float4*)(smem + sbuf * STAGE_B + S_SG + so);
            const float* ss = (const float*)&S;
            float tv[4];
#pragma unroll
            for (int u = 0; u < 4; u++) {
                bool on = ss[u] > 0.f;
                tv[u] = on ? 1.f : 0.f;
                zl[k] += on ? 1 : 0;
                sl[k] += ss[u];
            }
            const uint32_t sw = swz64(row * 64 + c8 * 8);
            sts_4bf16(t_tgt + sw, tv[0], tv[1], tv[2], tv[3]);
            sts_4bf16(t_sgm + sw, ss[0], ss[1], ss[2], ss[3]);
        }

        // refill consumed stage (self-ordered: we just read these bytes)
        if (kt + 2 < KT) ISSUE_STAGE(kt + 2, kt & 1);
        else asm volatile("cp.async.commit_group;");

        __syncthreads();   // tiles visible

        // ---- MMA phase ----
#pragma unroll
        for (int s = 0; s < 2; s++) {
            const int kbyte = s * 32;
            unsigned af[2][4], bfr[4][2];
#pragma unroll
            for (int mi = 0; mi < 2; mi++) {
                int row = wm * 32 + mi * 16 + (lane & 15);
                uint32_t addr = t_xw + swz64(row * 64 + kbyte + ((lane >> 4) << 4));
                asm volatile("ldmatrix.sync.aligned.m8n8.x4.shared.b16 {%0,%1,%2,%3},[%4];"
                             : "=r"(af[mi][0]), "=r"(af[mi][1]), "=r"(af[mi][2]), "=r"(af[mi][3])
                             : "r"(addr));
            }
#pragma unroll
            for (int ni = 0; ni < 4; ni++) {
                int l = lane & 15;
                int row = wn * 32 + ni * 8 + (l & 7);
                uint32_t addr = t_tgt + swz64(row * 64 + kbyte + ((l >> 3) << 4));
                asm volatile("ldmatrix.sync.aligned.m8n8.x2.shared.b16 {%0,%1},[%2];"
                             : "=r"(bfr[ni][0]), "=r"(bfr[ni][1]) : "r"(addr));
            }
#pragma unroll
            for (int mi = 0; mi < 2; mi++)
#pragma unroll
                for (int ni = 0; ni < 4; ni++)
                    asm volatile(
                        "mma.sync.aligned.m16n8k16.row.col.f32.bf16.bf16.f32 "
                        "{%0,%1,%2,%3},{%4,%5,%6,%7},{%8,%9},{%0,%1,%2,%3};\n"
                        : "+f"(acc1[mi][ni][0]), "+f"(acc1[mi][ni][1]),
                          "+f"(acc1[mi][ni][2]), "+f"(acc1[mi][ni][3])
                        : "r"(af[mi][0]), "r"(af[mi][1]), "r"(af[mi][2]), "r"(af[mi][3]),
                          "r"(bfr[ni][0]), "r"(bfr[ni][1]));
#pragma unroll
            for (int mi = 0; mi < 2; mi++) {
                int row = wm * 32 + mi * 16 + (lane & 15);
                uint32_t addr = t_p + swz64(row * 64 + kbyte + ((lane >> 4) << 4));
                asm volatile("ldmatrix.sync.aligned.m8n8.x4.shared.b16 {%0,%1,%2,%3},[%4];"
                             : "=r"(af[mi][0]), "=r"(af[mi][1]), "=r"(af[mi][2]), "=r"(af[mi][3])
                             : "r"(addr));
            }
#pragma unroll
            for (int ni = 0; ni < 4; ni++) {
                int l = lane & 15;
                int row = wn * 32 + ni * 8 + (l & 7);
                uint32_t addr = t_sgm + swz64(row * 64 + kbyte + ((l >> 3) << 4));
                asm volatile("ldmatrix.sync.aligned.m8n8.x2.shared.b16 {%0,%1},[%2];"
                             : "=r"(bfr[ni][0]), "=r"(bfr[ni][1]) : "r"(addr));
            }
#pragma unroll
            for (int mi = 0; mi < 2; mi++)
#pragma unroll
                for (int ni = 0; ni < 4; ni++)
                    asm volatile(
                        "mma.sync.aligned.m16n8k16.row.col.f32.bf16.bf16.f32 "
                        "{%0,%1,%2,%3},{%4,%5,%6,%7},{%8,%9},{%0,%1,%2,%3};\n"
                        : "+f"(acc2[mi][ni][0]), "+f"(acc2[mi][ni][1]),
                          "+f"(acc2[mi][ni][2]), "+f"(acc2[mi][ni][3])
                        : "r"(af[mi][0]), "r"(af[mi][1]), "r"(af[mi][2]), "r"(af[mi][3]),
                          "r"(bfr[ni][0]), "r"(bfr[ni][1]));
        }
        __syncthreads();   // MMA done; next transform may overwrite tiles
    }
#undef ISSUE_STAGE

    // ---- row-sum partials (8-thread butterfly over c8) ----
#pragma unroll
    for (int k = 0; k < 2; k++) {
        float v = nl[k], w2 = plo[k];
#pragma unroll
        for (int o = 4; o; o >>= 1) {
            v  += __shfl_xor_sync(0xffffffffu, v, o);
            w2 += __shfl_xor_sync(0xffffffffu, w2, o);
        }
        if (c8 == 0) {
            int row = r0 + 32 * k;
            g_negsum_p[(b * NSPLIT + split) * QD + mtile * TM + row] = v;
            g_psum_p  [(b * NSPLIT + split) * QD + mtile * TM + row] = w2;
        }
    }
    if (mtile == 0) {
#pragma unroll
        for (int k = 0; k < 4; k++) {
            float v = sl[k];
#pragma unroll
            for (int o = 4; o; o >>= 1) v += __shfl_xor_sync(0xffffffffu, v, o);
            if (c8 == 0)
                g_segsum_p[(b * NSPLIT + split) * ED + r0 + 32 * k] = v;
        }
        int zt = zl[0] + zl[1] + zl[2] + zl[3];
#pragma unroll
        for (int o = 16; o; o >>= 1) zt += __shfl_xor_sync(0xffffffffu, zt, o);
        __shared__ int zsm[8];
        if (lane == 0) zsm[wid] = zt;
        __syncthreads();
        if (tid == 0) {
            int t = 0;
#pragma unroll
            for (int i = 0; i < 8; i++) t += zsm[i];
            g_nnzs[b * NSPLIT + split] = t;
        }
    }

    // ---- accumulators -> packed bf16x2 partials ----
    const size_t pbase = ((size_t)(b * NSPLIT + split) * QD + mtile * TM) * ED;
#pragma unroll
    for (int mi = 0; mi < 2; mi++) {
        int r = wm * 32 + mi * 16 + (lane >> 2);
#pragma unroll
        for (int ni = 0; ni < 4; ni++) {
            int cc = wn * 32 + ni * 8 + (lane & 3) * 2;
            __nv_bfloat162 a0 = __floats2bfloat162_rn(acc1[mi][ni][0], acc2[mi][ni][0]);
            __nv_bfloat162 a1 = __floats2bfloat162_rn(acc1[mi][ni][1], acc2[mi][ni][1]);
            __nv_bfloat162 a2 = __floats2bfloat162_rn(acc1[mi][ni][2], acc2[mi][ni][2]);
            __nv_bfloat162 a3 = __floats2bfloat162_rn(acc1[mi][ni][3], acc2[mi][ni][3]);
            *(uint2*)&g_P[pbase + (size_t)r * ED + cc] =
                make_uint2(*(uint32_t*)&a0, *(uint32_t*)&a1);
            *(uint2*)&g_P[pbase + (size_t)(r + 8) * ED + cc] =
                make_uint2(*(uint32_t*)&a2, *(uint32_t*)&a3);
        }
    }
}

// ---------------- single fused tail: split reduce + cost assembly ----------------
__global__ __launch_bounds__(256) void epilogue_kernel(
    const float* __restrict__ positions, const float* __restrict__ true_positions,
    const float* __restrict__ iel, float* __restrict__ out)
{
    int idx = blockIdx.x * 256 + threadIdx.x;
    int e = idx & (ED - 1);
    int q = (idx >> 7) & (QD - 1);
    int b = idx >> 15;

    size_t poff = ((size_t)(b * NSPLIT) * QD + q) * ED + e;
    float gxw = 0.f, gd = 0.f;
#pragma unroll
    for (int s = 0; s < NSPLIT; s++) {
        __nv_bfloat162 v = g_P[poff + (size_t)s * (QD * ED)];
        gxw += __low2float(v);
        gd  += __high2float(v);
    }

    float ns = 0.f, ps = 0.f, ss = 0.f; int nz = 0;
#pragma unroll
    for (int s = 0; s < NSPLIT; s++) {
        ns += g_negsum_p[(b * NSPLIT + s) * QD + q];
        ps += g_psum_p  [(b * NSPLIT + s) * QD + q];
        ss += g_segsum_p[(b * NSPLIT + s) * ED + e];
        nz += g_nnzs    [b * NSPLIT + s];
    }

    float bce  = (ns - gxw) / (float)nz;
    float dice = 1.f - (2.f * gd + 1.f) / (ps + ss + 1.f);

    float x = iel[b * QD + q];
    float cls = log1pf(__expf(-fabsf(x))) + fmaxf(-x, 0.f);

    float px = positions[(b * QD + q) * 2 + 0];
    float py = positions[(b * QD + q) * 2 + 1];
    float tx = true_positions[(b * ED + e) * 2 + 0];
    float ty = true_positions[(b * ED + e) * 2 + 1];
    float ax = fabsf(px - tx), ay = fabsf(py - ty);
    float hx = ax < 1.f ? 0.5f * ax * ax : ax - 0.5f;
    float hy = ay < 1.f ? 0.5f * ay * ay : ay - 0.5f;
    float dist = 0.5f * (hx + hy);

    out[idx] = cls + bce + dice + dist;
}

// ---------------- launch ----------------
extern "C" void kernel_launch(void* const* d_in, const int* in_sizes, int n_in,
                              void* d_out, int out_size)
{
    const float* mask_logits    = (const float*)d_in[0];
    const float* pred_mask      = (const float*)d_in[1];
    const float* portion_logits = (const float*)d_in[2];
    const float* segmap         = (const float*)d_in[3];
    const float* positions      = (const float*)d_in[4];
    const float* true_positions = (const float*)d_in[5];
    const float* iel            = (const float*)d_in[6];
    float* out = (float*)d_out;

    cudaFuncSetAttribute(fused_gemm_kernel,
                         cudaFuncAttributeMaxDynamicSharedMemorySize, SMEM_TOTAL);

    fused_gemm_kernel<<<BD * 4 * NSPLIT, 256, SMEM_TOTAL>>>(
        mask_logits, pred_mask, portion_logits, segmap);
    epilogue_kernel<<<(BD * QD * ED) / 256, 256>>>(positions, true_positions, iel, out);
}

// round 10
// speedup vs baseline: 1.6849x; 1.6849x over previous
#include <cuda_runtime.h>
#include <cuda_bf16.h>
#include <math.h>
#include <stdint.h>

#define HWD 36864
#define BD 4
#define QD 256
#define ED 128
#define NSPLIT 18
#define KS (HWD / NSPLIT)   // 2048
#define BK 32
#define KT (KS / BK)        // 64

// smem: 2 fp32 stage buffers + double-buffered bf16 tiles
#define STAGE_ARR 16384                  // 128 rows x 128B (32 fp32)
#define STAGE_B   (4 * STAGE_ARR)        // 65536
#define TILE_BB   8192                   // 128 rows x 64B (32 bf16)
#define TILE_SET  (4 * TILE_BB)          // 32768
#define SM_TILES  (2 * STAGE_B)          // 131072
#define SMEM_TOTAL (SM_TILES + 2 * TILE_SET)   // 196608

// ---------------- static scratch ----------------
__device__ __align__(16) __nv_bfloat162 g_P[(size_t)BD * NSPLIT * QD * ED];
__device__ float g_negsum_p[BD * NSPLIT * QD];
__device__ float g_psum_p  [BD * NSPLIT * QD];
__device__ float g_segsum_p[BD * NSPLIT * ED];
__device__ int   g_nnzs    [BD * NSPLIT];

__device__ __forceinline__ uint32_t swz64(int off) {
    return (uint32_t)(off ^ ((off >> 3) & 0x30));
}

__device__ __forceinline__ float fast_tanh(float x) {
    float y;
    asm("tanh.approx.f32 %0, %1;" : "=f"(y) : "f"(x));
    return y;
}

__device__ __forceinline__ void sts_4bf16(uint32_t addr, float a, float b,
                                          float c, float d) {
    __nv_bfloat162 lo = __floats2bfloat162_rn(a, b);
    __nv_bfloat162 hi = __floats2bfloat162_rn(c, d);
    asm volatile("st.shared.v2.b32 [%0], {%1,%2};"
                 :: "r"(addr), "r"(*(uint32_t*)&lo), "r"(*(uint32_t*)&hi));
}

#define CPA16(dst, src) \
    asm volatile("cp.async.cg.shared.global [%0], [%1], 16;" :: "r"(dst), "l"(src))

// ---------------- fused prep + 2x GEMM, phase-pipelined ----------------
__global__ __launch_bounds__(256, 1) void fused_gemm_kernel(
    const float* __restrict__ ml, const float* __restrict__ pm,
    const float* __restrict__ pl, const float* __restrict__ seg)
{
    extern __shared__ __align__(16) char smem[];
    const uint32_t smem_base = (uint32_t)__cvta_generic_to_shared(smem);
    const int tid = threadIdx.x;
    const int wid = tid >> 5, lane = tid & 31;

    int bx = blockIdx.x;                 // 0..143
    const int split = bx % NSPLIT; bx /= NSPLIT;
    const int mt = bx & 1;         bx >>= 1;
    const int b = bx;

    const int r0 = tid >> 3;              // 0..31
    const int c8 = tid & 7;               // 16B group within 128B K-chunk
    const size_t colg = (size_t)split * KS + c8 * 4;

    const float* gml = ml + ((size_t)(b * QD + mt * 128)) * HWD + colg;
    const float* gpm = pm + ((size_t)(b * QD + mt * 128)) * HWD + colg;
    const float* gpl = pl + ((size_t)(b * QD + mt * 128)) * HWD + colg;
    const float* gsg = seg + ((size_t)(b * ED)) * HWD + colg;

    const int wm = wid & 1;
    const int wn = wid >> 1;

    float acc1[4][4][4];
    float acc2[4][4][4];
#pragma unroll
    for (int mi = 0; mi < 4; mi++)
#pragma unroll
        for (int ni = 0; ni < 4; ni++)
#pragma unroll
            for (int c = 0; c < 4; c++) { acc1[mi][ni][c] = 0.f; acc2[mi][ni][c] = 0.f; }

    float nl[4], plo[4], sl[4]; int zl[4];
#pragma unroll
    for (int k = 0; k < 4; k++) { nl[k] = plo[k] = sl[k] = 0.f; zl[k] = 0; }

#define ISSUE_STAGE(kt_, buf_) do {                                            \
        const uint32_t sb = smem_base + (buf_) * STAGE_B;                      \
        const size_t kadv = (size_t)(kt_) * BK;                                \
        _Pragma("unroll")                                                      \
        for (int k_ = 0; k_ < 4; k_++) {                                       \
            const int row_ = r0 + 32 * k_;                                     \
            const uint32_t so = row_ * 128 + c8 * 16;                          \
            const size_t go = (size_t)row_ * HWD + kadv;                       \
            CPA16(sb + 0 * STAGE_ARR + so, gml + go);                          \
            CPA16(sb + 1 * STAGE_ARR + so, gpm + go);                          \
            CPA16(sb + 2 * STAGE_ARR + so, gpl + go);                          \
            CPA16(sb + 3 * STAGE_ARR + so, gsg + go);                          \
        }                                                                      \
        asm volatile("cp.async.commit_group;");                                \
    } while (0)

// transform chunks [KF, KT_) of stage buffer sbuf_ into tile set tset_
#define TCHUNKS(sbuf_, tset_, KF, KTo) do {                                    \
        _Pragma("unroll")                                                      \
        for (int k = (KF); k < (KTo); k++) {                                   \
            const int row = r0 + 32 * k;                                       \
            const uint32_t so = row * 128 + c8 * 16;                           \
            float4 M = *(const float4*)(smem + (sbuf_) * STAGE_B + 0 * STAGE_ARR + so); \
            float4 W = *(const float4*)(smem + (sbuf_) * STAGE_B + 1 * STAGE_ARR + so); \
            float4 L = *(const float4*)(smem + (sbuf_) * STAGE_B + 2 * STAGE_ARR + so); \
            float4 S = *(const float4*)(smem + (sbuf_) * STAGE_B + 3 * STAGE_ARR + so); \
            const float* mm = (const float*)&M;                                \
            const float* ww = (const float*)&W;                                \
            const float* ll = (const float*)&L;                                \
            const float* ss = (const float*)&S;                                \
            float xw[4], qv[4], tv[4];                                         \
            _Pragma("unroll")                                                  \
            for (int u = 0; u < 4; u++) {                                      \
                float x = mm[u], wt = ww[u];                                   \
                xw[u] = x * wt;                                                \
                float sx = 0.5f + 0.5f * fast_tanh(0.5f * x);                  \
                nl[k] += -__logf(fmaxf(1.f - sx, 1e-30f)) * wt;                \
                qv[u] = wt * (0.5f + 0.5f * fast_tanh(0.5f * ll[u]));          \
                plo[k] += qv[u];                                               \
                bool on = ss[u] > 0.f;                                         \
                tv[u] = on ? 1.f : 0.f;                                        \
                zl[k] += on ? 1 : 0;                                           \
                sl[k] += ss[u];                                                \
            }                                                                  \
            const uint32_t sw = swz64(row * 64 + c8 * 8);                      \
            sts_4bf16((tset_) + 0 * TILE_BB + sw, xw[0], xw[1], xw[2], xw[3]); \
            sts_4bf16((tset_) + 1 * TILE_BB + sw, qv[0], qv[1], qv[2], qv[3]); \
            sts_4bf16((tset_) + 2 * TILE_BB + sw, tv[0], tv[1], tv[2], tv[3]); \
            sts_4bf16((tset_) + 3 * TILE_BB + sw, ss[0], ss[1], ss[2], ss[3]); \
        }                                                                      \
    } while (0)

// one K=16 MMA slice (s_) on tile set pset_
#define MMA_HALF(pset_, s_) do {                                               \
        const int kbyte = (s_) * 32;                                           \
        unsigned af[4][4], bfr[4][2];                                          \
        _Pragma("unroll")                                                      \
        for (int mi = 0; mi < 4; mi++) {                                       \
            int row = wm * 64 + mi * 16 + (lane & 15);                         \
            uint32_t addr = (pset_) + 0 * TILE_BB + swz64(row * 64 + kbyte + ((lane >> 4) << 4)); \
            asm volatile("ldmatrix.sync.aligned.m8n8.x4.shared.b16 {%0,%1,%2,%3},[%4];" \
                         : "=r"(af[mi][0]), "=r"(af[mi][1]), "=r"(af[mi][2]), "=r"(af[mi][3]) \
                         : "r"(addr));                                         \
        }                                                                      \
        _Pragma("unroll")                                                      \
        for (int ni = 0; ni < 4; ni++) {                                       \
            int l = lane & 15;                                                 \
            int row = wn * 32 + ni * 8 + (l & 7);                              \
            uint32_t addr = (pset_) + 2 * TILE_BB + swz64(row * 64 + kbyte + ((l >> 3) << 4)); \
            asm volatile("ldmatrix.sync.aligned.m8n8.x2.shared.b16 {%0,%1},[%2];" \
                         : "=r"(bfr[ni][0]), "=r"(bfr[ni][1]) : "r"(addr));    \
        }                                                                      \
        _Pragma("unroll")                                                      \
        for (int mi = 0; mi < 4; mi++)                                         \
            _Pragma("unroll")                                                  \
            for (int ni = 0; ni < 4; ni++)                                     \
                asm volatile(                                                  \
                    "mma.sync.aligned.m16n8k16.row.col.f32.bf16.bf16.f32 "     \
                    "{%0,%1,%2,%3},{%4,%5,%6,%7},{%8,%9},{%0,%1,%2,%3};\n"     \
                    : "+f"(acc1[mi][ni][0]), "+f"(acc1[mi][ni][1]),            \
                      "+f"(acc1[mi][ni][2]), "+f"(acc1[mi][ni][3])             \
                    : "r"(af[mi][0]), "r"(af[mi][1]), "r"(af[mi][2]), "r"(af[mi][3]), \
                      "r"(bfr[ni][0]), "r"(bfr[ni][1]));                       \
        _Pragma("unroll")                                                      \
        for (int mi = 0; mi < 4; mi++) {                                       \
            int row = wm * 64 + mi * 16 + (lane & 15);                         \
            uint32_t addr = (pset_) + 1 * TILE_BB + swz64(row * 64 + kbyte + ((lane >> 4) << 4)); \
            asm volatile("ldmatrix.sync.aligned.m8n8.x4.shared.b16 {%0,%1,%2,%3},[%4];" \
                         : "=r"(af[mi][0]), "=r"(af[mi][1]), "=r"(af[mi][2]), "=r"(af[mi][3]) \
                         : "r"(addr));                                         \
        }                                                                      \
        _Pragma("unroll")                                                      \
        for (int ni = 0; ni < 4; ni++) {                                       \
            int l = lane & 15;                                                 \
            int row = wn * 32 + ni * 8 + (l & 7);                              \
            uint32_t addr = (pset_) + 3 * TILE_BB + swz64(row * 64 + kbyte + ((l >> 3) << 4)); \
            asm volatile("ldmatrix.sync.aligned.m8n8.x2.shared.b16 {%0,%1},[%2];" \
                         : "=r"(bfr[ni][0]), "=r"(bfr[ni][1]) : "r"(addr));    \
        }                                                                      \
        _Pragma("unroll")                                                      \
        for (int mi = 0; mi < 4; mi++)                                         \
            _Pragma("unroll")                                                  \
            for (int ni = 0; ni < 4; ni++)                                     \
                asm volatile(                                                  \
                    "mma.sync.aligned.m16n8k16.row.col.f32.bf16.bf16.f32 "     \
                    "{%0,%1,%2,%3},{%4,%5,%6,%7},{%8,%9},{%0,%1,%2,%3};\n"     \
                    : "+f"(acc2[mi][ni][0]), "+f"(acc2[mi][ni][1]),            \
                      "+f"(acc2[mi][ni][2]), "+f"(acc2[mi][ni][3])             \
                    : "r"(af[mi][0]), "r"(af[mi][1]), "r"(af[mi][2]), "r"(af[mi][3]), \
                      "r"(bfr[ni][0]), "r"(bfr[ni][1]));                       \
    } while (0)

    const uint32_t tiles0 = smem_base + SM_TILES;
    const uint32_t tiles1 = smem_base + SM_TILES + TILE_SET;

    // ---- prologue: stages 0,1 in flight; transform(0) ----
    ISSUE_STAGE(0, 0);
    ISSUE_STAGE(1, 1);
    asm volatile("cp.async.wait_group 1;" ::: "memory");
    TCHUNKS(0, tiles0, 0, 4);
    ISSUE_STAGE(2, 0);
    __syncthreads();

    // ---- pipelined mainloop: transform(kt) || MMA(kt-1) ----
    for (int kt = 1; kt < KT; kt++) {
        asm volatile("cp.async.wait_group 1;" ::: "memory");
        const int sbuf = kt & 1;
        const uint32_t tset = sbuf ? tiles1 : tiles0;   // tiles for kt
        const uint32_t pset = sbuf ? tiles0 : tiles1;   // tiles for kt-1

        TCHUNKS(sbuf, tset, 0, 2);
        MMA_HALF(pset, 0);
        TCHUNKS(sbuf, tset, 2, 4);
        MMA_HALF(pset, 1);

        if (kt + 2 < KT) ISSUE_STAGE(kt + 2, sbuf);
        else asm volatile("cp.async.commit_group;");
        __syncthreads();
    }
    // ---- epilogue MMA on the last tiles ----
    {
        const uint32_t pset = ((KT - 1) & 1) ? tiles1 : tiles0;
        MMA_HALF(pset, 0);
        MMA_HALF(pset, 1);
    }
#undef ISSUE_STAGE
#undef TCHUNKS
#undef MMA_HALF

    // ---- row-sum partials (8-thread butterfly over c8) ----
#pragma unroll
    for (int k = 0; k < 4; k++) {
        float v = nl[k], w2 = plo[k];
#pragma unroll
        for (int o = 4; o; o >>= 1) {
            v  += __shfl_xor_sync(0xffffffffu, v, o);
            w2 += __shfl_xor_sync(0xffffffffu, w2, o);
        }
        if (c8 == 0) {
            int row = r0 + 32 * k;
            g_negsum_p[(b * NSPLIT + split) * QD + mt * 128 + row] = v;
            g_psum_p  [(b * NSPLIT + split) * QD + mt * 128 + row] = w2;
        }
    }
    if (mt == 0) {
#pragma unroll
        for (int k = 0; k < 4; k++) {
            float v = sl[k];
#pragma unroll
            for (int o = 4; o; o >>= 1) v += __shfl_xor_sync(0xffffffffu, v, o);
            if (c8 == 0)
                g_segsum_p[(b * NSPLIT + split) * ED + r0 + 32 * k] = v;
        }
        int zt = zl[0] + zl[1] + zl[2] + zl[3];
#pragma unroll
        for (int o = 16; o; o >>= 1) zt += __shfl_xor_sync(0xffffffffu, zt, o);
        __shared__ int zsm[8];
        if (lane == 0) zsm[wid] = zt;
        __syncthreads();
        if (tid == 0) {
            int t = 0;
#pragma unroll
            for (int i = 0; i < 8; i++) t += zsm[i];
            g_nnzs[b * NSPLIT + split] = t;
        }
    }

    // ---- accumulators -> packed bf16x2 partials ----
    const size_t pbase = ((size_t)(b * NSPLIT + split) * QD + mt * 128) * ED;
#pragma unroll
    for (int mi = 0; mi < 4; mi++) {
        int r = wm * 64 + mi * 16 + (lane >> 2);
#pragma unroll
        for (int ni = 0; ni < 4; ni++) {
            int cc = wn * 32 + ni * 8 + (lane & 3) * 2;
            __nv_bfloat162 a0 = __floats2bfloat162_rn(acc1[mi][ni][0], acc2[mi][ni][0]);
            __nv_bfloat162 a1 = __floats2bfloat162_rn(acc1[mi][ni][1], acc2[mi][ni][1]);
            __nv_bfloat162 a2 = __floats2bfloat162_rn(acc1[mi][ni][2], acc2[mi][ni][2]);
            __nv_bfloat162 a3 = __floats2bfloat162_rn(acc1[mi][ni][3], acc2[mi][ni][3]);
            *(uint2*)&g_P[pbase + (size_t)r * ED + cc] =
                make_uint2(*(uint32_t*)&a0, *(uint32_t*)&a1);
            *(uint2*)&g_P[pbase + (size_t)(r + 8) * ED + cc] =
                make_uint2(*(uint32_t*)&a2, *(uint32_t*)&a3);
        }
    }
}

// ---------------- single fused tail: split reduce + cost assembly ----------------
__global__ __launch_bounds__(256) void epilogue_kernel(
    const float* __restrict__ positions, const float* __restrict__ true_positions,
    const float* __restrict__ iel, float* __restrict__ out)
{
    int idx = blockIdx.x * 256 + threadIdx.x;
    int e = idx & (ED - 1);
    int q = (idx >> 7) & (QD - 1);
    int b = idx >> 15;

    size_t poff = ((size_t)(b * NSPLIT) * QD + q) * ED + e;
    float gxw = 0.f, gd = 0.f;
#pragma unroll
    for (int s = 0; s < NSPLIT; s++) {
        __nv_bfloat162 v = g_P[poff + (size_t)s * (QD * ED)];
        gxw += __low2float(v);
        gd  += __high2float(v);
    }

    float ns = 0.f, ps = 0.f, ss = 0.f; int nz = 0;
#pragma unroll
    for (int s = 0; s < NSPLIT; s++) {
        ns += g_negsum_p[(b * NSPLIT + s) * QD + q];
        ps += g_psum_p  [(b * NSPLIT + s) * QD + q];
        ss += g_segsum_p[(b * NSPLIT + s) * ED + e];
        nz += g_nnzs    [b * NSPLIT + s];
    }

    float bce  = (ns - gxw) / (float)nz;
    float dice = 1.f - (2.f * gd + 1.f) / (ps + ss + 1.f);

    float x = iel[b * QD + q];
    float cls = log1pf(__expf(-fabsf(x))) + fmaxf(-x, 0.f);

    float px = positions[(b * QD + q) * 2 + 0];
    float py = positions[(b * QD + q) * 2 + 1];
    float tx = true_positions[(b * ED + e) * 2 + 0];
    float ty = true_positions[(b * ED + e) * 2 + 1];
    float ax = fabsf(px - tx), ay = fabsf(py - ty);
    float hx = ax < 1.f ? 0.5f * ax * ax : ax - 0.5f;
    float hy = ay < 1.f ? 0.5f * ay * ay : ay - 0.5f;
    float dist = 0.5f * (hx + hy);

    out[idx] = cls + bce + dice + dist;
}

// ---------------- launch ----------------
extern "C" void kernel_launch(void* const* d_in, const int* in_sizes, int n_in,
                              void* d_out, int out_size)
{
    const float* mask_logits    = (const float*)d_in[0];
    const float* pred_mask      = (const float*)d_in[1];
    const float* portion_logits = (const float*)d_in[2];
    const float* segmap         = (const float*)d_in[3];
    const float* positions      = (const float*)d_in[4];
    const float* true_positions = (const float*)d_in[5];
    const float* iel            = (const float*)d_in[6];
    float* out = (float*)d_out;

    cudaFuncSetAttribute(fused_gemm_kernel,
                         cudaFuncAttributeMaxDynamicSharedMemorySize, SMEM_TOTAL);

    fused_gemm_kernel<<<BD * 2 * NSPLIT, 256, SMEM_TOTAL>>>(
        mask_logits, pred_mask, portion_logits, segmap);
    epilogue_kernel<<<(BD * QD * ED) / 256, 256>>>(positions, true_positions, iel, out);
}